// round 1
// baseline (speedup 1.0000x reference)
#include <cuda_runtime.h>
#include <cuda_bf16.h>
#include <math.h>

#define C_DIM 256
#define NTOK 2048          // 64 * 32 tokens per side per batch
#define SB_COUNT 16        // side(2) * batch(8)

// ---------------- scratch (static device globals; no allocation) ----------------
__device__ float g_q[SB_COUNT * NTOK * C_DIM];
__device__ float g_k[SB_COUNT * NTOK * C_DIM];
__device__ float g_v[SB_COUNT * NTOK * C_DIM];
__device__ float g_att[SB_COUNT * NTOK * C_DIM];        // ctx per head, pre out-proj
__device__ float g_ctxT[SB_COUNT * C_DIM * NTOK];       // out-proj result, transposed [sb][c][n]
__device__ float g_inwT[C_DIM * 768];                   // in_w^T  : [c][co]
__device__ float g_outwT[C_DIM * C_DIM];                // out_w^T : [c][co]
__device__ float g_projwT[1024 * C_DIM];                // proj_w^T: [j][co]

// ---------------- K0: transpose weights ----------------
__global__ void transpose_weights(const float* __restrict__ in_w,
                                  const float* __restrict__ out_w,
                                  const float* __restrict__ proj_w) {
    int i = blockIdx.x * blockDim.x + threadIdx.x;
    if (i < 768 * 256) { int co = i >> 8;  int c = i & 255;  g_inwT[c * 768 + co]  = in_w[i]; }
    if (i < 256 * 256) { int co = i >> 8;  int c = i & 255;  g_outwT[c * 256 + co] = out_w[i]; }
    if (i < 256 * 1024){ int co = i >> 10; int j = i & 1023; g_projwT[j * 256 + co] = proj_w[i]; }
}

// ---------------- K1: QKV GEMM ----------------
// out[sb, n, co3] for co3 in [0,768): co3<256 -> q from qf-gather; else k/v from mirror-gather.
// BM=128, BN=128, BK=8, 256 threads, 8x8 per-thread tile.
__global__ void __launch_bounds__(256) qkv_gemm(const float* __restrict__ feat,
                                                const float* __restrict__ in_b) {
    const int co0 = blockIdx.x * 128;
    const int m0  = blockIdx.y * 128;
    const int sb  = blockIdx.z;
    const int side = sb >> 3, b = sb & 7;
    const bool is_q = (co0 < 256);
    const float* featB = feat + (size_t)b * (C_DIM * 4096);

    __shared__ float As[8][128];
    __shared__ float Bs[8][128];

    const int t = threadIdx.x;
    const int tx = t & 15, ty = t >> 4;
    float acc[8][8];
#pragma unroll
    for (int i = 0; i < 8; ++i)
#pragma unroll
        for (int j = 0; j < 8; ++j) acc[i][j] = 0.0f;

    // A gather spatial offset for this thread's mm (constant across k-steps)
    const int mm = t & 127;
    const int m  = m0 + mm;
    const int yq = m >> 5, xq = m & 31;
    const int col = is_q ? (side ? 32 + xq : xq) : (side ? 31 - xq : 63 - xq);
    const int aoff = yq * 64 + col;

    for (int kt = 0; kt < 32; ++kt) {
        const int c0 = kt * 8;
#pragma unroll
        for (int i = 0; i < 4; ++i) {
            int kk = (t + i * 256) >> 7;       // t>>7 + 2*i
            As[kk][mm] = featB[(size_t)(c0 + kk) * 4096 + aoff];
        }
#pragma unroll
        for (int i = 0; i < 4; ++i) {
            int flat = t + i * 256;
            int kk = flat >> 7, jj = flat & 127;
            Bs[kk][jj] = g_inwT[(c0 + kk) * 768 + co0 + jj];
        }
        __syncthreads();
#pragma unroll
        for (int kk = 0; kk < 8; ++kk) {
            float4 a0 = *(const float4*)&As[kk][ty * 8];
            float4 a1 = *(const float4*)&As[kk][ty * 8 + 4];
            float4 b0 = *(const float4*)&Bs[kk][tx * 8];
            float4 b1 = *(const float4*)&Bs[kk][tx * 8 + 4];
            float a[8]  = {a0.x, a0.y, a0.z, a0.w, a1.x, a1.y, a1.z, a1.w};
            float bb[8] = {b0.x, b0.y, b0.z, b0.w, b1.x, b1.y, b1.z, b1.w};
#pragma unroll
            for (int i = 0; i < 8; ++i)
#pragma unroll
                for (int j = 0; j < 8; ++j) acc[i][j] += a[i] * bb[j];
        }
        __syncthreads();
    }

    const size_t rowbase = (size_t)sb * NTOK;
#pragma unroll
    for (int i = 0; i < 8; ++i) {
        int mw = m0 + ty * 8 + i;
#pragma unroll
        for (int j = 0; j < 8; ++j) {
            int co = co0 + tx * 8 + j;
            float val = acc[i][j] + in_b[co];
            float* dst = (co < 256) ? g_q : ((co < 512) ? g_k : g_v);
            dst[(rowbase + mw) * C_DIM + (co & 255)] = val;
        }
    }
}

// ---------------- K2: sparse attention (<=13 neighbors, Manhattan radius 2) ----------------
// One warp per (sb, head, token). Lane l handles d = l and l+32.
__global__ void __launch_bounds__(256) attn_kernel() {
    const int wgid = blockIdx.x * 8 + (threadIdx.x >> 5);
    const int lane = threadIdx.x & 31;
    const int n  = wgid & 2047;
    const int hd = (wgid >> 11) & 3;
    const int sb = wgid >> 13;
    const int y = n >> 5, x = n & 31;

    const float* qb = g_q + ((size_t)sb * NTOK + n) * C_DIM + hd * 64;
    const float q0 = qb[lane];
    const float q1 = qb[lane + 32];

    const int ody[13] = {0, 0, 0, 0, 0, -1, -1, -1, 1, 1, 1, -2, 2};
    const int odx[13] = {0,-1, 1,-2, 2,  0, -1,  1, 0,-1, 1,  0, 0};
    float sc[13];
    int   midx[13];

#pragma unroll
    for (int i = 0; i < 13; ++i) {
        int yy = y + ody[i], xx = x + odx[i];
        bool valid = (yy >= 0) && (yy < 64) && (xx >= 0) && (xx < 32);
        int mm = valid ? (yy * 32 + xx) : n;
        midx[i] = valid ? mm : -1;
        const float* kb = g_k + ((size_t)sb * NTOK + mm) * C_DIM + hd * 64;
        float s = q0 * kb[lane] + q1 * kb[lane + 32];
#pragma unroll
        for (int o = 16; o > 0; o >>= 1) s += __shfl_xor_sync(0xffffffffu, s, o);
        sc[i] = valid ? s * 0.125f : -1e30f;
    }

    float mx = -1e30f;
#pragma unroll
    for (int i = 0; i < 13; ++i) mx = fmaxf(mx, sc[i]);
    float ssum = 0.0f;
#pragma unroll
    for (int i = 0; i < 13; ++i) {
        sc[i] = (midx[i] >= 0) ? __expf(sc[i] - mx) : 0.0f;
        ssum += sc[i];
    }
    const float inv = 1.0f / ssum;

    float a0 = 0.0f, a1 = 0.0f;
#pragma unroll
    for (int i = 0; i < 13; ++i) {
        if (midx[i] >= 0) {
            const float* vb = g_v + ((size_t)sb * NTOK + midx[i]) * C_DIM + hd * 64;
            float w = sc[i] * inv;
            a0 += w * vb[lane];
            a1 += w * vb[lane + 32];
        }
    }
    float* ob = g_att + ((size_t)sb * NTOK + n) * C_DIM + hd * 64;
    ob[lane]      = a0;
    ob[lane + 32] = a1;
}

// ---------------- K3: out-proj GEMM (writes transposed ctx) ----------------
// BM=128, BN=128, BK=8. A = g_att [row][256] contiguous.
__global__ void __launch_bounds__(256) outproj_gemm(const float* __restrict__ out_b) {
    const int co0 = blockIdx.x * 128;
    const int m0  = blockIdx.y * 128;
    const int sb  = blockIdx.z;

    __shared__ float As[128][8];   // [mm][kk]
    __shared__ float Bs[8][128];

    const int t = threadIdx.x;
    const int tx = t & 15, ty = t >> 4;
    float acc[8][8];
#pragma unroll
    for (int i = 0; i < 8; ++i)
#pragma unroll
        for (int j = 0; j < 8; ++j) acc[i][j] = 0.0f;

    const size_t rowbase = (size_t)sb * NTOK;
    const float* Arow = g_att + (rowbase + m0) * C_DIM;
    const int lmm = t >> 1;
    const int lcc = (t & 1) * 4;

    for (int kt = 0; kt < 32; ++kt) {
        const int c0 = kt * 8;
        *(float4*)&As[lmm][lcc] = *(const float4*)&Arow[lmm * C_DIM + c0 + lcc];
#pragma unroll
        for (int i = 0; i < 4; ++i) {
            int flat = t + i * 256;
            int kk = flat >> 7, jj = flat & 127;
            Bs[kk][jj] = g_outwT[(c0 + kk) * 256 + co0 + jj];
        }
        __syncthreads();
#pragma unroll
        for (int kk = 0; kk < 8; ++kk) {
            float a[8];
#pragma unroll
            for (int i = 0; i < 8; ++i) a[i] = As[ty * 8 + i][kk];
            float4 b0 = *(const float4*)&Bs[kk][tx * 8];
            float4 b1 = *(const float4*)&Bs[kk][tx * 8 + 4];
            float bb[8] = {b0.x, b0.y, b0.z, b0.w, b1.x, b1.y, b1.z, b1.w};
#pragma unroll
            for (int i = 0; i < 8; ++i)
#pragma unroll
                for (int j = 0; j < 8; ++j) acc[i][j] += a[i] * bb[j];
        }
        __syncthreads();
    }

#pragma unroll
    for (int i = 0; i < 8; ++i) {
        int mw = m0 + ty * 8 + i;
#pragma unroll
        for (int j = 0; j < 8; ++j) {
            int co = co0 + tx * 8 + j;
            g_ctxT[((size_t)sb * C_DIM + co) * NTOK + mw] = acc[i][j] + out_b[co];
        }
    }
}

// ---------------- K4: fused asym-concat + proj GEMM + LayerNorm + ReLU ----------------
// BM=64, BN=256 (full row), BK=8. warp = 8 rows; lane = 8 cols. LN via warp shuffles.
__global__ void __launch_bounds__(256) fused_proj_ln(const float* __restrict__ feat,
                                                     const float* __restrict__ proj_b,
                                                     const float* __restrict__ ln_g,
                                                     const float* __restrict__ ln_b,
                                                     float* __restrict__ out) {
    const int m0 = blockIdx.y * 64;
    const int sb = blockIdx.z;
    const int side = sb >> 3, b = sb & 7;
    const float* featB = feat + (size_t)b * (C_DIM * 4096);
    const float* ctxTB = g_ctxT + (size_t)sb * C_DIM * NTOK;

    __shared__ float As[64][9];     // padded: conflict-free STS
    __shared__ float Bs[8][256];

    const int t = threadIdx.x;
    const int lane = t & 31;
    const int warp = t >> 5;        // 0..7 -> row group
    float acc[8][8];
#pragma unroll
    for (int i = 0; i < 8; ++i)
#pragma unroll
        for (int j = 0; j < 8; ++j) acc[i][j] = 0.0f;

    const int lmm  = t & 63;
    const int lkk0 = t >> 6;        // 0..3
    const int lm   = m0 + lmm;
    const int ly = lm >> 5, lx = lm & 31;
    const int lxq = side ? (32 + lx) : lx;
    const int qoff = ly * 64 + lxq;

    for (int kt = 0; kt < 128; ++kt) {
        const int j0 = kt * 8;
        const int part = j0 >> 8;   // uniform per k-step (8 | 256)
#pragma unroll
        for (int i = 0; i < 2; ++i) {
            int kk = lkk0 + i * 4;
            int jc = (j0 + kk) & 255;
            float val;
            if (part == 0) {
                val = featB[(size_t)jc * 4096 + qoff];
            } else if (part == 1) {
                val = ctxTB[(size_t)jc * NTOK + lm];
            } else {
                float qv = featB[(size_t)jc * 4096 + qoff];
                float cv = ctxTB[(size_t)jc * NTOK + lm];
                val = (part == 2) ? fabsf(qv - cv) : qv * cv;
            }
            As[lmm][kk] = val;
        }
#pragma unroll
        for (int i = 0; i < 8; ++i) {
            int flat = t + i * 256;
            int kk = flat >> 8, jj = flat & 255;
            Bs[kk][jj] = g_projwT[(j0 + kk) * 256 + jj];
        }
        __syncthreads();
#pragma unroll
        for (int kk = 0; kk < 8; ++kk) {
            float a[8];
#pragma unroll
            for (int i = 0; i < 8; ++i) a[i] = As[warp * 8 + i][kk];
            float4 b0 = *(const float4*)&Bs[kk][lane * 8];
            float4 b1 = *(const float4*)&Bs[kk][lane * 8 + 4];
            float bb[8] = {b0.x, b0.y, b0.z, b0.w, b1.x, b1.y, b1.z, b1.w};
#pragma unroll
            for (int i = 0; i < 8; ++i)
#pragma unroll
                for (int j = 0; j < 8; ++j) acc[i][j] += a[i] * bb[j];
        }
        __syncthreads();
    }

    // epilogue: bias + LayerNorm(256) + relu + transposed scatter to output
    float g[8], btn[8];
#pragma unroll
    for (int j = 0; j < 8; ++j) {
        int co = lane * 8 + j;
        float pb = proj_b[co];
        g[j]   = ln_g[co];
        btn[j] = ln_b[co];
#pragma unroll
        for (int i = 0; i < 8; ++i) acc[i][j] += pb;
    }

#pragma unroll
    for (int i = 0; i < 8; ++i) {
        float s1 = 0.0f, s2 = 0.0f;
#pragma unroll
        for (int j = 0; j < 8; ++j) { s1 += acc[i][j]; s2 += acc[i][j] * acc[i][j]; }
#pragma unroll
        for (int o = 16; o > 0; o >>= 1) {
            s1 += __shfl_xor_sync(0xffffffffu, s1, o);
            s2 += __shfl_xor_sync(0xffffffffu, s2, o);
        }
        const float mu   = s1 * (1.0f / 256.0f);
        const float var  = s2 * (1.0f / 256.0f) - mu * mu;
        const float rstd = rsqrtf(var + 1e-5f);

        const int mw = m0 + warp * 8 + i;
        const int y = mw >> 5, x = mw & 31;
        const int xg = side ? (32 + x) : x;
#pragma unroll
        for (int j = 0; j < 8; ++j) {
            int co = lane * 8 + j;
            float vv = (acc[i][j] - mu) * rstd * g[j] + btn[j];
            out[(((size_t)b * C_DIM + co) * 64 + y) * 64 + xg] = fmaxf(vv, 0.0f);
        }
    }
}

// ---------------- launch ----------------
extern "C" void kernel_launch(void* const* d_in, const int* in_sizes, int n_in,
                              void* d_out, int out_size) {
    const float* feat   = (const float*)d_in[0];
    const float* in_w   = (const float*)d_in[1];
    const float* in_b   = (const float*)d_in[2];
    const float* out_w  = (const float*)d_in[3];
    const float* out_b  = (const float*)d_in[4];
    const float* proj_w = (const float*)d_in[5];
    const float* proj_b = (const float*)d_in[6];
    const float* ln_g   = (const float*)d_in[7];
    const float* ln_b   = (const float*)d_in[8];
    float* out = (float*)d_out;

    transpose_weights<<<1024, 256>>>(in_w, out_w, proj_w);
    qkv_gemm<<<dim3(6, 16, 16), 256>>>(feat, in_b);
    attn_kernel<<<16384, 256>>>();
    outproj_gemm<<<dim3(2, 16, 16), 256>>>(out_b);
    fused_proj_ln<<<dim3(1, 32, 16), 256>>>(feat, proj_b, ln_g, ln_b, out);
}

// round 4
// speedup vs baseline: 2.9241x; 2.9241x over previous
#include <cuda_runtime.h>
#include <cstdint>
#include <math.h>

#define C_DIM 256
#define NTOK 2048          // 64 * 32 tokens per side per batch
#define SB_COUNT 16        // side(2) * batch(8)

// ---------------- scratch (static device globals; no allocation) ----------------
__device__ float g_q[SB_COUNT * NTOK * C_DIM];
__device__ float g_k[SB_COUNT * NTOK * C_DIM];
__device__ float g_v[SB_COUNT * NTOK * C_DIM];
__device__ float g_att[SB_COUNT * NTOK * C_DIM];
__device__ float g_ctxT[SB_COUNT * C_DIM * NTOK];       // [sb][c][n]
__device__ float g_inwT[C_DIM * 768];                   // in_w^T  (tf32-rounded)
__device__ float g_outwT[C_DIM * C_DIM];                // out_w^T (tf32-rounded)
__device__ float g_projwT[1024 * C_DIM];                // proj_w^T(tf32-rounded)

// ---------------- helpers ----------------
__device__ __forceinline__ uint32_t f2tf(float x) {
    uint32_t u; asm("cvt.rna.tf32.f32 %0, %1;" : "=r"(u) : "f"(x)); return u;
}
__device__ __forceinline__ void mma8(float* c, const uint32_t* a, const uint32_t* b) {
    asm volatile("mma.sync.aligned.m16n8k8.row.col.f32.tf32.tf32.f32 "
        "{%0,%1,%2,%3}, {%4,%5,%6,%7}, {%8,%9}, {%0,%1,%2,%3};"
        : "+f"(c[0]), "+f"(c[1]), "+f"(c[2]), "+f"(c[3])
        : "r"(a[0]), "r"(a[1]), "r"(a[2]), "r"(a[3]), "r"(b[0]), "r"(b[1]));
}

// ---------------- K0: transpose + tf32-round weights ----------------
__global__ void transpose_weights(const float* __restrict__ in_w,
                                  const float* __restrict__ out_w,
                                  const float* __restrict__ proj_w) {
    int i = blockIdx.x * blockDim.x + threadIdx.x;
    if (i < 768 * 256) { int co = i >> 8;  int c = i & 255;  g_inwT[c * 768 + co]  = __uint_as_float(f2tf(in_w[i])); }
    if (i < 256 * 256) { int co = i >> 8;  int c = i & 255;  g_outwT[c * 256 + co] = __uint_as_float(f2tf(out_w[i])); }
    if (i < 256 * 1024){ int co = i >> 10; int j = i & 1023; g_projwT[j * 256 + co] = __uint_as_float(f2tf(proj_w[i])); }
}

// ---------------- K1: QKV GEMM (tf32 mma) ----------------
// BM=128 BN=128 BK=16, 256 thr, warp tile 64x32
__global__ void __launch_bounds__(256) qkv_gemm(const float* __restrict__ feat,
                                                const float* __restrict__ in_b) {
    const int co0 = blockIdx.x * 128;
    const int m0  = blockIdx.y * 128;
    const int sb  = blockIdx.z;
    const int side = sb >> 3, b = sb & 7;
    const bool is_q = (co0 < 256);
    const float* featB = feat + (size_t)b * (C_DIM * 4096);

    __shared__ uint32_t As[16][136];
    __shared__ uint32_t Bs[16][136];

    const int t = threadIdx.x;
    const int w = t >> 5, lane = t & 31, quad = lane >> 2, tq = lane & 3;
    const int mw = (w & 1) * 64, nw = (w >> 1) * 32;

    float acc[4][4][4];
#pragma unroll
    for (int i = 0; i < 4; ++i)
#pragma unroll
        for (int j = 0; j < 4; ++j)
#pragma unroll
            for (int p = 0; p < 4; ++p) acc[i][j][p] = 0.0f;

    const int mm = t & 127;
    const int m  = m0 + mm;
    const int yq = m >> 5, xq = m & 31;
    const int colg = is_q ? (side ? 32 + xq : xq) : (side ? 31 - xq : 63 - xq);
    const int aoff = yq * 64 + colg;
    const int jj = t & 127;
    const int kb0 = t >> 7;   // 0 or 1

    float ra[8], rb[8];
#pragma unroll
    for (int i = 0; i < 8; ++i) {
        ra[i] = featB[(size_t)(kb0 + 2 * i) * 4096 + aoff];
        rb[i] = g_inwT[(kb0 + 2 * i) * 768 + co0 + jj];
    }

    for (int kt = 0; kt < 16; ++kt) {
#pragma unroll
        for (int i = 0; i < 8; ++i) {
            As[kb0 + 2 * i][mm] = f2tf(ra[i]);
            Bs[kb0 + 2 * i][jj] = __float_as_uint(rb[i]);
        }
        __syncthreads();
        if (kt < 15) {
            const int c0 = (kt + 1) * 16;
#pragma unroll
            for (int i = 0; i < 8; ++i) {
                ra[i] = featB[(size_t)(c0 + kb0 + 2 * i) * 4096 + aoff];
                rb[i] = g_inwT[(c0 + kb0 + 2 * i) * 768 + co0 + jj];
            }
        }
#pragma unroll
        for (int k0 = 0; k0 < 16; k0 += 8) {
            uint32_t af[4][4], bf[4][2];
#pragma unroll
            for (int i = 0; i < 4; ++i) {
                af[i][0] = As[k0 + tq][mw + i * 16 + quad];
                af[i][1] = As[k0 + tq][mw + i * 16 + quad + 8];
                af[i][2] = As[k0 + tq + 4][mw + i * 16 + quad];
                af[i][3] = As[k0 + tq + 4][mw + i * 16 + quad + 8];
            }
#pragma unroll
            for (int j = 0; j < 4; ++j) {
                bf[j][0] = Bs[k0 + tq][nw + j * 8 + quad];
                bf[j][1] = Bs[k0 + tq + 4][nw + j * 8 + quad];
            }
#pragma unroll
            for (int i = 0; i < 4; ++i)
#pragma unroll
                for (int j = 0; j < 4; ++j)
                    mma8(acc[i][j], af[i], bf[j]);
        }
        __syncthreads();
    }

    const size_t rowbase = (size_t)sb * NTOK;
#pragma unroll
    for (int i = 0; i < 4; ++i) {
        int r0 = m0 + mw + i * 16 + quad;
#pragma unroll
        for (int j = 0; j < 4; ++j) {
            int co = co0 + nw + j * 8 + tq * 2;
            float b0 = in_b[co], b1 = in_b[co + 1];
            float* dst = (co < 256) ? g_q : ((co < 512) ? g_k : g_v);
            int cl = co & 255;
            float2 v0 = make_float2(acc[i][j][0] + b0, acc[i][j][1] + b1);
            float2 v1 = make_float2(acc[i][j][2] + b0, acc[i][j][3] + b1);
            *(float2*)&dst[(rowbase + r0) * C_DIM + cl]     = v0;
            *(float2*)&dst[(rowbase + r0 + 8) * C_DIM + cl] = v1;
        }
    }
}

// ---------------- K2: sparse attention (fp32, warp per token-head) ----------------
__global__ void __launch_bounds__(256) attn_kernel() {
    const int wgid = blockIdx.x * 8 + (threadIdx.x >> 5);
    const int lane = threadIdx.x & 31;
    const int n  = wgid & 2047;
    const int hd = (wgid >> 11) & 3;
    const int sb = wgid >> 13;
    const int y = n >> 5, x = n & 31;

    const float* qb = g_q + ((size_t)sb * NTOK + n) * C_DIM + hd * 64;
    const float q0 = qb[lane];
    const float q1 = qb[lane + 32];

    const int ody[13] = {0, 0, 0, 0, 0, -1, -1, -1, 1, 1, 1, -2, 2};
    const int odx[13] = {0,-1, 1,-2, 2,  0, -1,  1, 0,-1, 1,  0, 0};
    float sc[13];
    int   midx[13];

#pragma unroll
    for (int i = 0; i < 13; ++i) {
        int yy = y + ody[i], xx = x + odx[i];
        bool valid = (yy >= 0) && (yy < 64) && (xx >= 0) && (xx < 32);
        int mm = valid ? (yy * 32 + xx) : n;
        midx[i] = valid ? mm : -1;
        const float* kb = g_k + ((size_t)sb * NTOK + mm) * C_DIM + hd * 64;
        float s = q0 * kb[lane] + q1 * kb[lane + 32];
#pragma unroll
        for (int o = 16; o > 0; o >>= 1) s += __shfl_xor_sync(0xffffffffu, s, o);
        sc[i] = valid ? s * 0.125f : -1e30f;
    }

    float mx = -1e30f;
#pragma unroll
    for (int i = 0; i < 13; ++i) mx = fmaxf(mx, sc[i]);
    float ssum = 0.0f;
#pragma unroll
    for (int i = 0; i < 13; ++i) {
        sc[i] = (midx[i] >= 0) ? __expf(sc[i] - mx) : 0.0f;
        ssum += sc[i];
    }
    const float inv = 1.0f / ssum;

    float a0 = 0.0f, a1 = 0.0f;
#pragma unroll
    for (int i = 0; i < 13; ++i) {
        if (midx[i] >= 0) {
            const float* vb = g_v + ((size_t)sb * NTOK + midx[i]) * C_DIM + hd * 64;
            float wgt = sc[i] * inv;
            a0 += wgt * vb[lane];
            a1 += wgt * vb[lane + 32];
        }
    }
    float* ob = g_att + ((size_t)sb * NTOK + n) * C_DIM + hd * 64;
    ob[lane]      = a0;
    ob[lane + 32] = a1;
}

// ---------------- K3: out-proj GEMM (tf32 mma), writes transposed ctx ----------------
__global__ void __launch_bounds__(256) outproj_gemm(const float* __restrict__ out_b) {
    const int co0 = blockIdx.x * 128;
    const int m0  = blockIdx.y * 128;
    const int sb  = blockIdx.z;

    __shared__ uint32_t As[16][136];
    __shared__ uint32_t Bs[16][136];

    const int t = threadIdx.x;
    const int w = t >> 5, lane = t & 31, quad = lane >> 2, tq = lane & 3;
    const int mw = (w & 1) * 64, nw = (w >> 1) * 32;

    float acc[4][4][4];
#pragma unroll
    for (int i = 0; i < 4; ++i)
#pragma unroll
        for (int j = 0; j < 4; ++j)
#pragma unroll
            for (int p = 0; p < 4; ++p) acc[i][j][p] = 0.0f;

    const float* Arow = g_att + ((size_t)sb * NTOK + m0) * C_DIM;
    const int akk = t & 15, amb = t >> 4;   // mm = amb + 16*i
    const int jj = t & 127, kb0 = t >> 7;

    float ra[8], rb[8];
#pragma unroll
    for (int i = 0; i < 8; ++i) {
        ra[i] = Arow[(amb + 16 * i) * C_DIM + akk];
        rb[i] = g_outwT[(kb0 + 2 * i) * 256 + co0 + jj];
    }

    for (int kt = 0; kt < 16; ++kt) {
#pragma unroll
        for (int i = 0; i < 8; ++i) {
            As[akk][amb + 16 * i] = f2tf(ra[i]);
            Bs[kb0 + 2 * i][jj] = __float_as_uint(rb[i]);
        }
        __syncthreads();
        if (kt < 15) {
            const int c0 = (kt + 1) * 16;
#pragma unroll
            for (int i = 0; i < 8; ++i) {
                ra[i] = Arow[(amb + 16 * i) * C_DIM + c0 + akk];
                rb[i] = g_outwT[(c0 + kb0 + 2 * i) * 256 + co0 + jj];
            }
        }
#pragma unroll
        for (int k0 = 0; k0 < 16; k0 += 8) {
            uint32_t af[4][4], bf[4][2];
#pragma unroll
            for (int i = 0; i < 4; ++i) {
                af[i][0] = As[k0 + tq][mw + i * 16 + quad];
                af[i][1] = As[k0 + tq][mw + i * 16 + quad + 8];
                af[i][2] = As[k0 + tq + 4][mw + i * 16 + quad];
                af[i][3] = As[k0 + tq + 4][mw + i * 16 + quad + 8];
            }
#pragma unroll
            for (int j = 0; j < 4; ++j) {
                bf[j][0] = Bs[k0 + tq][nw + j * 8 + quad];
                bf[j][1] = Bs[k0 + tq + 4][nw + j * 8 + quad];
            }
#pragma unroll
            for (int i = 0; i < 4; ++i)
#pragma unroll
                for (int j = 0; j < 4; ++j)
                    mma8(acc[i][j], af[i], bf[j]);
        }
        __syncthreads();
    }

#pragma unroll
    for (int i = 0; i < 4; ++i) {
        int r0 = m0 + mw + i * 16 + quad;
#pragma unroll
        for (int j = 0; j < 4; ++j) {
            int co = co0 + nw + j * 8 + tq * 2;
            float b0 = out_b[co], b1 = out_b[co + 1];
            float* base = g_ctxT + (size_t)sb * C_DIM * NTOK;
            base[(size_t)co * NTOK + r0]           = acc[i][j][0] + b0;
            base[(size_t)(co + 1) * NTOK + r0]     = acc[i][j][1] + b1;
            base[(size_t)co * NTOK + r0 + 8]       = acc[i][j][2] + b0;
            base[(size_t)(co + 1) * NTOK + r0 + 8] = acc[i][j][3] + b1;
        }
    }
}

// ---------------- K4: fused asym-concat + proj (tf32 mma) + LayerNorm + ReLU ----------------
// BM=128, BN=256 (full row), BK=16, 512 thr, warp tile 32x64 (4 m-warps x 4 n-warps)
__global__ void __launch_bounds__(512) fused_proj_ln(const float* __restrict__ feat,
                                                     const float* __restrict__ proj_b,
                                                     const float* __restrict__ ln_g,
                                                     const float* __restrict__ ln_b,
                                                     float* __restrict__ out) {
    const int m0 = blockIdx.y * 128;
    const int sb = blockIdx.z;
    const int side = sb >> 3, b = sb & 7;
    const float* featB = feat + (size_t)b * (C_DIM * 4096);
    const float* ctxTB = g_ctxT + (size_t)sb * C_DIM * NTOK;

    __shared__ uint32_t As[16][136];
    __shared__ uint32_t Bs[16][264];
    __shared__ float2 red[128][4];

    const int t = threadIdx.x;
    const int w = t >> 5, lane = t & 31, quad = lane >> 2, tq = lane & 3;
    const int wm = w & 3, nwi = w >> 2;
    const int mw = wm * 32, nwcol = nwi * 64;

    float acc[2][8][4];
#pragma unroll
    for (int i = 0; i < 2; ++i)
#pragma unroll
        for (int j = 0; j < 8; ++j)
#pragma unroll
            for (int p = 0; p < 4; ++p) acc[i][j][p] = 0.0f;

    const int amm = t & 127, akb = t >> 7;       // kk = akb + 4*i
    const int lm = m0 + amm;
    const int ly = lm >> 5, lx = lm & 31;
    const int qoff = ly * 64 + (side ? 32 + lx : lx);
    const int bjj = t & 255, bkb = t >> 8;       // kk = bkb + 2*i

    float rq[4], rc[4], rb[8];

    // prefetch kt=0 (part 0: qt only)
#pragma unroll
    for (int i = 0; i < 4; ++i)
        rq[i] = featB[(size_t)(akb + 4 * i) * 4096 + qoff];
#pragma unroll
    for (int i = 0; i < 8; ++i)
        rb[i] = g_projwT[(bkb + 2 * i) * 256 + bjj];
#pragma unroll
    for (int i = 0; i < 4; ++i) rc[i] = 0.0f;

    for (int kt = 0; kt < 64; ++kt) {
        const int part = kt >> 4;
#pragma unroll
        for (int i = 0; i < 4; ++i) {
            float v;
            if (part == 0)      v = rq[i];
            else if (part == 1) v = rc[i];
            else if (part == 2) v = fabsf(rq[i] - rc[i]);
            else                v = rq[i] * rc[i];
            As[akb + 4 * i][amm] = f2tf(v);
        }
#pragma unroll
        for (int i = 0; i < 8; ++i) Bs[bkb + 2 * i][bjj] = __float_as_uint(rb[i]);
        __syncthreads();

        if (kt < 63) {
            const int j0 = (kt + 1) * 16;
            const int np = j0 >> 8;
#pragma unroll
            for (int i = 0; i < 4; ++i) {
                int jc = (j0 + akb + 4 * i) & 255;
                if (np != 1) rq[i] = featB[(size_t)jc * 4096 + qoff];
                if (np != 0) rc[i] = ctxTB[(size_t)jc * NTOK + lm];
            }
#pragma unroll
            for (int i = 0; i < 8; ++i)
                rb[i] = g_projwT[(j0 + bkb + 2 * i) * 256 + bjj];
        }

#pragma unroll
        for (int k0 = 0; k0 < 16; k0 += 8) {
            uint32_t af[2][4], bf[8][2];
#pragma unroll
            for (int i = 0; i < 2; ++i) {
                af[i][0] = As[k0 + tq][mw + i * 16 + quad];
                af[i][1] = As[k0 + tq][mw + i * 16 + quad + 8];
                af[i][2] = As[k0 + tq + 4][mw + i * 16 + quad];
                af[i][3] = As[k0 + tq + 4][mw + i * 16 + quad + 8];
            }
#pragma unroll
            for (int j = 0; j < 8; ++j) {
                bf[j][0] = Bs[k0 + tq][nwcol + j * 8 + quad];
                bf[j][1] = Bs[k0 + tq + 4][nwcol + j * 8 + quad];
            }
#pragma unroll
            for (int i = 0; i < 2; ++i)
#pragma unroll
                for (int j = 0; j < 8; ++j)
                    mma8(acc[i][j], af[i], bf[j]);
        }
        __syncthreads();
    }

    // ---- epilogue: +bias, LN(256), relu, transposed scatter ----
#pragma unroll
    for (int j = 0; j < 8; ++j) {
        int co = nwcol + j * 8 + tq * 2;
        float2 pb = *(const float2*)&proj_b[co];
#pragma unroll
        for (int i = 0; i < 2; ++i) {
            acc[i][j][0] += pb.x; acc[i][j][1] += pb.y;
            acc[i][j][2] += pb.x; acc[i][j][3] += pb.y;
        }
    }

#pragma unroll
    for (int i = 0; i < 2; ++i)
#pragma unroll
        for (int u = 0; u < 2; ++u) {
            float s1 = 0.0f, s2 = 0.0f;
#pragma unroll
            for (int j = 0; j < 8; ++j) {
                float x0 = acc[i][j][2 * u], x1 = acc[i][j][2 * u + 1];
                s1 += x0 + x1; s2 += x0 * x0 + x1 * x1;
            }
            s1 += __shfl_xor_sync(0xffffffffu, s1, 1);
            s2 += __shfl_xor_sync(0xffffffffu, s2, 1);
            s1 += __shfl_xor_sync(0xffffffffu, s1, 2);
            s2 += __shfl_xor_sync(0xffffffffu, s2, 2);
            if (tq == 0) {
                int r = mw + i * 16 + u * 8 + quad;
                red[r][nwi] = make_float2(s1, s2);
            }
        }
    __syncthreads();

#pragma unroll
    for (int i = 0; i < 2; ++i)
#pragma unroll
        for (int u = 0; u < 2; ++u) {
            int r = mw + i * 16 + u * 8 + quad;
            float s1 = 0.0f, s2 = 0.0f;
#pragma unroll
            for (int p = 0; p < 4; ++p) { float2 v = red[r][p]; s1 += v.x; s2 += v.y; }
            float mu   = s1 * (1.0f / 256.0f);
            float var  = s2 * (1.0f / 256.0f) - mu * mu;
            float rstd = rsqrtf(var + 1e-5f);

            int grow = m0 + r;
            int y = grow >> 5, x = grow & 31;
            int xg = side ? (32 + x) : x;
            size_t obase = (size_t)b * C_DIM * 4096 + y * 64 + xg;
#pragma unroll
            for (int j = 0; j < 8; ++j) {
                int co = nwcol + j * 8 + tq * 2;
                float g0 = ln_g[co], g1 = ln_g[co + 1];
                float l0 = ln_b[co], l1 = ln_b[co + 1];
                float v0 = fmaxf((acc[i][j][2 * u]     - mu) * rstd * g0 + l0, 0.0f);
                float v1 = fmaxf((acc[i][j][2 * u + 1] - mu) * rstd * g1 + l1, 0.0f);
                out[obase + (size_t)co * 4096]       = v0;
                out[obase + (size_t)(co + 1) * 4096] = v1;
            }
        }
}

// ---------------- launch ----------------
extern "C" void kernel_launch(void* const* d_in, const int* in_sizes, int n_in,
                              void* d_out, int out_size) {
    const float* feat   = (const float*)d_in[0];
    const float* in_w   = (const float*)d_in[1];
    const float* in_b   = (const float*)d_in[2];
    const float* out_w  = (const float*)d_in[3];
    const float* out_b  = (const float*)d_in[4];
    const float* proj_w = (const float*)d_in[5];
    const float* proj_b = (const float*)d_in[6];
    const float* ln_g   = (const float*)d_in[7];
    const float* ln_b   = (const float*)d_in[8];
    float* out = (float*)d_out;

    transpose_weights<<<1024, 256>>>(in_w, out_w, proj_w);
    qkv_gemm<<<dim3(6, 16, 16), 256>>>(feat, in_b);
    attn_kernel<<<16384, 256>>>();
    outproj_gemm<<<dim3(2, 16, 16), 256>>>(out_b);
    fused_proj_ln<<<dim3(1, 16, 16), 512>>>(feat, proj_b, ln_g, ln_b, out);
}